// round 13
// baseline (speedup 1.0000x reference)
#include <cuda_runtime.h>
#include <cuda_fp16.h>
#include <cstdint>
#include <math.h>

#define NROWS   100000
#define NFEAT   512
#define NHID    256
#define NCLASS  41
#define TPH     48          // t row pitch in halves (41 used)
#define W2PN    64          // W2 padded cols

// ---------------- scratch (device globals) ----------------------------------
__device__ float4 g_buf1_v[(size_t)NROWS * NHID / 4];   // XW1 (half), then t (half)
__device__ float4 g_buf2_v[(size_t)NROWS * NHID / 4];   // h (half)
__device__ int    g_rowptr[NROWS + 1];
__device__ __align__(16) uint32_t g_w1p[(NFEAT / 2) * NHID];
__device__ __align__(16) uint32_t g_w2p[(NHID / 2) * W2PN];

// ---------------- row_ptr ----------------------------------------------------
__global__ void build_rowptr(const int* __restrict__ rows, int nnz) {
    int i = blockIdx.x * blockDim.x + threadIdx.x;
    if (i > NROWS) return;
    int lo = 0, hi = nnz;
    while (lo < hi) {
        int mid = (lo + hi) >> 1;
        if (rows[mid] < i) lo = mid + 1; else hi = mid;
    }
    g_rowptr[i] = lo;
}

// ---------------- mma helper ---------------------------------------------------
__device__ __forceinline__ void mma_f16(float* c, const uint32_t* a, const uint32_t* b) {
    asm volatile(
        "mma.sync.aligned.m16n8k16.row.col.f32.f16.f16.f32 "
        "{%0,%1,%2,%3}, {%4,%5,%6,%7}, {%8,%9}, {%0,%1,%2,%3};"
        : "+f"(c[0]), "+f"(c[1]), "+f"(c[2]), "+f"(c[3])
        : "r"(a[0]), "r"(a[1]), "r"(a[2]), "r"(a[3]),
          "r"(b[0]), "r"(b[1]));
}

// ---------------- prep: half2-packed W1 + W2 (merged) ------------------------
#define W1PN_ELEMS ((NFEAT / 2) * NHID)
#define W2PN_ELEMS ((NHID / 2) * W2PN)
__global__ void prep_w(const float* __restrict__ w1, const float* __restrict__ w2) {
    int i = blockIdx.x * blockDim.x + threadIdx.x;
    if (i < W1PN_ELEMS) {
        int k2 = i / NHID, n = i % NHID;
        __half2 u = __halves2half2(__float2half_rn(w1[(2 * k2) * NHID + n]),
                                   __float2half_rn(w1[(2 * k2 + 1) * NHID + n]));
        g_w1p[i] = *(uint32_t*)&u;
    } else if (i < W1PN_ELEMS + W2PN_ELEMS) {
        int j = i - W1PN_ELEMS;
        int k2 = j / W2PN, n = j % W2PN;
        __half2 u = (n < NCLASS)
            ? __halves2half2(__float2half_rn(w2[(2 * k2) * NCLASS + n]),
                             __float2half_rn(w2[(2 * k2 + 1) * NCLASS + n]))
            : __halves2half2(__float2half_rn(0.f), __float2half_rn(0.f));
        g_w2p[j] = *(uint32_t*)&u;
    }
}

// ---------------- SGEMM1: FP16 m16n8k16, double-buffered, half out -----------
// One launch covers ONE 128-col half (col0 param) so spmm1 can overlap.
#define BM 128
#define BN 128
#define FBK 32
#define SAP 20
#define SBP 136

__device__ __forceinline__ void f_ldgA(const float* A, int row0, int k0, int tid,
                                       float4 ra[4]) {
#pragma unroll
    for (int q = 0; q < 4; q++) {
        int idx = q * 256 + tid;
        int r = idx >> 3, c4 = (idx & 7) * 4;
        float4 v = {0.f, 0.f, 0.f, 0.f};
        if (row0 + r < NROWS)
            v = *(const float4*)(A + (size_t)(row0 + r) * NFEAT + k0 + c4);
        ra[q] = v;
    }
}
__device__ __forceinline__ void f_ldgB(const uint32_t* Bp, int col0, int k0, int tid,
                                       uint4 rb[2]) {
    int k20 = k0 / 2;
#pragma unroll
    for (int q = 0; q < 2; q++) {
        int idx = q * 256 + tid;
        int r = idx >> 5, c4 = (idx & 31) * 4;
        rb[q] = *(const uint4*)(Bp + (size_t)(k20 + r) * NHID + col0 + c4);
    }
}
__device__ __forceinline__ void f_sts(uint32_t (*sA)[SAP], uint32_t (*sB)[SBP],
                                      int tid, const float4 ra[4], const uint4 rb[2]) {
#pragma unroll
    for (int q = 0; q < 4; q++) {
        int idx = q * 256 + tid;
        int r = idx >> 3, c2 = (idx & 7) * 2;
        __half2 h0 = __floats2half2_rn(ra[q].x, ra[q].y);
        __half2 h1 = __floats2half2_rn(ra[q].z, ra[q].w);
        sA[r][c2]     = *(uint32_t*)&h0;
        sA[r][c2 + 1] = *(uint32_t*)&h1;
    }
#pragma unroll
    for (int q = 0; q < 2; q++) {
        int idx = q * 256 + tid;
        int r = idx >> 5, c4 = (idx & 31) * 4;
        *(uint4*)&sB[r][c4] = rb[q];
    }
}

__global__ __launch_bounds__(256) void sgemm_f16(const float* __restrict__ A,
                                                 const uint32_t* __restrict__ Bp,
                                                 __half* __restrict__ C,
                                                 int col0) {
    __shared__ __align__(16) uint32_t sA[2][BM][SAP];
    __shared__ __align__(16) uint32_t sB[2][FBK / 2][SBP];

    const int tid  = threadIdx.x;
    const int lane = tid & 31;
    const int warp = tid >> 5;
    const int warp_m = warp & 1;
    const int warp_n = warp >> 1;
    const int row0 = blockIdx.x * BM;
    const int tr = lane >> 2;
    const int tc = lane & 3;

    float acc[4][4][4];
#pragma unroll
    for (int i = 0; i < 4; i++)
#pragma unroll
        for (int j = 0; j < 4; j++)
#pragma unroll
            for (int q = 0; q < 4; q++) acc[i][j][q] = 0.f;

    float4 ra[4]; uint4 rb[2];
    f_ldgA(A, row0, 0, tid, ra);
    f_ldgB(Bp, col0, 0, tid, rb);
    f_sts(sA[0], sB[0], tid, ra, rb);
    __syncthreads();

    const int NT = NFEAT / FBK;
    for (int t = 0; t < NT; t++) {
        const int cur = t & 1;
        if (t + 1 < NT) {
            f_ldgA(A, row0, (t + 1) * FBK, tid, ra);
            f_ldgB(Bp, col0, (t + 1) * FBK, tid, rb);
        }
#pragma unroll
        for (int s = 0; s < 2; s++) {
            const int kb = s * 8;
            uint32_t bf[4][2];
#pragma unroll
            for (int wn = 0; wn < 4; wn++) {
                int n = warp_n * 32 + wn * 8 + tr;
                bf[wn][0] = sB[cur][kb + tc][n];
                bf[wn][1] = sB[cur][kb + tc + 4][n];
            }
#pragma unroll
            for (int wm = 0; wm < 4; wm++) {
                int m = warp_m * 64 + wm * 16 + tr;
                uint32_t af[4];
                af[0] = sA[cur][m][kb + tc];
                af[1] = sA[cur][m + 8][kb + tc];
                af[2] = sA[cur][m][kb + tc + 4];
                af[3] = sA[cur][m + 8][kb + tc + 4];
#pragma unroll
                for (int wn = 0; wn < 4; wn++)
                    mma_f16(acc[wm][wn], af, bf[wn]);
            }
        }
        if (t + 1 < NT)
            f_sts(sA[cur ^ 1], sB[cur ^ 1], tid, ra, rb);
        __syncthreads();
    }

#pragma unroll
    for (int wm = 0; wm < 4; wm++) {
        int r = row0 + warp_m * 64 + wm * 16 + tr;
#pragma unroll
        for (int wn = 0; wn < 4; wn++) {
            int c = col0 + warp_n * 32 + wn * 8 + tc * 2;
            if (r < NROWS) {
                __half2 hv = __floats2half2_rn(acc[wm][wn][0], acc[wm][wn][1]);
                *(uint32_t*)(C + (size_t)r * NHID + c) = *(uint32_t*)&hv;
            }
            if (r + 8 < NROWS) {
                __half2 hv = __floats2half2_rn(acc[wm][wn][2], acc[wm][wn][3]);
                *(uint32_t*)(C + (size_t)(r + 8) * NHID + c) = *(uint32_t*)&hv;
            }
        }
    }
}

// ---------------- SpMM layer 1: fp16, col-chunked (128 halves/chunk) ---------
// warp per row; lane covers 4 halves (uint2) of the chunk. fp32 acc; half out.
__global__ __launch_bounds__(256) void spmm1_chunkh(const int* __restrict__ cols,
                                                    const float* __restrict__ vals,
                                                    const uint2* __restrict__ denseH,
                                                    const float* __restrict__ bias,
                                                    uint2* __restrict__ outH,
                                                    int chunk) {
    int row  = blockIdx.x * 8 + (threadIdx.x >> 5);
    if (row >= NROWS) return;
    int lane = threadIdx.x & 31;
    const int u2off = chunk * 32 + lane;       // uint2 index within 64-uint2 row

    int s = g_rowptr[row];
    int e = g_rowptr[row + 1];

    float acc[4] = {0.f, 0.f, 0.f, 0.f};
    for (int j = s; j < e; j++) {
        int   c = __ldg(cols + j);
        float v = __ldg(vals + j);
        uint2 d = __ldg(denseH + (size_t)c * (NHID / 4) + u2off);
        float2 f0 = __half22float2(*(const __half2*)&d.x);
        float2 f1 = __half22float2(*(const __half2*)&d.y);
        acc[0] += v * f0.x; acc[1] += v * f0.y;
        acc[2] += v * f1.x; acc[3] += v * f1.y;
    }

    const int c0 = u2off * 4;
    float4 b = __ldg((const float4*)(bias + c0));
    acc[0] = fmaxf(acc[0] + b.x, 0.f); acc[1] = fmaxf(acc[1] + b.y, 0.f);
    acc[2] = fmaxf(acc[2] + b.z, 0.f); acc[3] = fmaxf(acc[3] + b.w, 0.f);

    uint2 o;
    __half2 hv0 = __floats2half2_rn(acc[0], acc[1]);
    __half2 hv1 = __floats2half2_rn(acc[2], acc[3]);
    o.x = *(uint32_t*)&hv0;
    o.y = *(uint32_t*)&hv1;
    outH[(size_t)row * (NHID / 4) + u2off] = o;
}

// ---------------- t = h @ W2  fp16 m16n8k16 (128x64 tile) --------------------
#define TBM 128
#define TBK 64
#define TSAP 36
#define TSBP 72

__global__ __launch_bounds__(256) void gemm_t_h(const __half* __restrict__ H,
                                                const uint32_t* __restrict__ Bp,
                                                __half* __restrict__ T) {
    __shared__ __align__(16) uint32_t sA[TBM][TSAP];
    __shared__ __align__(16) uint32_t sB[TBK / 2][TSBP];

    const int tid  = threadIdx.x;
    const int lane = tid & 31;
    const int warp = tid >> 5;
    const int warp_m = warp & 1;
    const int warp_n = warp >> 1;
    const int row0 = blockIdx.x * TBM;
    const int tr = lane >> 2;
    const int tc = lane & 3;

    float acc[4][2][4];
#pragma unroll
    for (int i = 0; i < 4; i++)
#pragma unroll
        for (int j = 0; j < 2; j++)
#pragma unroll
            for (int q = 0; q < 4; q++) acc[i][j][q] = 0.f;

    for (int k0 = 0; k0 < NHID; k0 += TBK) {
#pragma unroll
        for (int q = 0; q < 4; q++) {
            int idx = q * 256 + tid;
            int r = idx >> 3, c8 = (idx & 7) * 8;
            uint4 v = {0u, 0u, 0u, 0u};
            if (row0 + r < NROWS)
                v = *(const uint4*)(H + (size_t)(row0 + r) * NHID + k0 + c8);
            *(uint4*)&sA[r][c8 / 2] = v;
        }
        {
            int k20 = k0 / 2;
#pragma unroll
            for (int q = 0; q < 2; q++) {
                int idx = q * 256 + tid;
                int r = idx >> 4, c4 = (idx & 15) * 4;
                *(uint4*)&sB[r][c4] = *(const uint4*)(Bp + (size_t)(k20 + r) * W2PN + c4);
            }
        }
        __syncthreads();

#pragma unroll
        for (int s = 0; s < 4; s++) {
            const int kb = s * 8;
            uint32_t bf[2][2];
#pragma unroll
            for (int wn = 0; wn < 2; wn++) {
                int n = warp_n * 16 + wn * 8 + tr;
                bf[wn][0] = sB[kb + tc][n];
                bf[wn][1] = sB[kb + tc + 4][n];
            }
#pragma unroll
            for (int wm = 0; wm < 4; wm++) {
                int m = warp_m * 64 + wm * 16 + tr;
                uint32_t af[4];
                af[0] = sA[m][kb + tc];
                af[1] = sA[m + 8][kb + tc];
                af[2] = sA[m][kb + tc + 4];
                af[3] = sA[m + 8][kb + tc + 4];
#pragma unroll
                for (int wn = 0; wn < 2; wn++)
                    mma_f16(acc[wm][wn], af, bf[wn]);
            }
        }
        __syncthreads();
    }

#pragma unroll
    for (int wm = 0; wm < 4; wm++) {
        int r = row0 + warp_m * 64 + wm * 16 + tr;
#pragma unroll
        for (int wn = 0; wn < 2; wn++) {
            int c = warp_n * 16 + wn * 8 + tc * 2;
            if (c < TPH) {
                if (r < NROWS) {
                    __half2 hv = __floats2half2_rn(acc[wm][wn][0], acc[wm][wn][1]);
                    *(uint32_t*)(T + (size_t)r * TPH + c) = *(uint32_t*)&hv;
                }
                if (r + 8 < NROWS) {
                    __half2 hv = __floats2half2_rn(acc[wm][wn][2], acc[wm][wn][3]);
                    *(uint32_t*)(T + (size_t)(r + 8) * TPH + c) = *(uint32_t*)&hv;
                }
            }
        }
    }
}

// ---------------- SpMM layer 2 + b2 + log_softmax (fp16 t, 2 rows/warp) ------
__global__ __launch_bounds__(256) void spmm2_lsm(const int* __restrict__ cols,
                                                 const float* __restrict__ vals,
                                                 const uint2* __restrict__ tH,
                                                 const float* __restrict__ b2,
                                                 float* __restrict__ out) {
    int lane   = threadIdx.x & 31;
    int lane16 = lane & 15;
    int row = blockIdx.x * 16 + (threadIdx.x >> 5) * 2 + (lane >> 4);
    if (row >= NROWS) return;
    const bool active = lane16 < (TPH / 4);    // 12 of 16 half-warp lanes

    int s = g_rowptr[row];
    int e = g_rowptr[row + 1];

    float acc[4] = {0.f, 0.f, 0.f, 0.f};
    for (int j = s; j < e; j++) {
        int   c = __ldg(cols + j);
        float v = __ldg(vals + j);
        if (active) {
            uint2 d = __ldg(tH + (size_t)c * (TPH / 4) + lane16);
            float2 f0 = __half22float2(*(const __half2*)&d.x);
            float2 f1 = __half22float2(*(const __half2*)&d.y);
            acc[0] += v * f0.x; acc[1] += v * f0.y;
            acc[2] += v * f1.x; acc[3] += v * f1.y;
        }
    }

    float z[4];
    const int c0 = lane16 * 4;
#pragma unroll
    for (int i = 0; i < 4; i++) {
        int c = c0 + i;
        z[i] = (active && c < NCLASS) ? (acc[i] + __ldg(b2 + c)) : -INFINITY;
    }
    float m = fmaxf(fmaxf(z[0], z[1]), fmaxf(z[2], z[3]));
#pragma unroll
    for (int off = 8; off; off >>= 1)
        m = fmaxf(m, __shfl_xor_sync(0xFFFFFFFFu, m, off));

    float ss = 0.f;
#pragma unroll
    for (int i = 0; i < 4; i++)
        if (c0 + i < NCLASS) ss += expf(z[i] - m);
#pragma unroll
    for (int off = 8; off; off >>= 1)
        ss += __shfl_xor_sync(0xFFFFFFFFu, ss, off);

    float lse = m + logf(ss);
#pragma unroll
    for (int i = 0; i < 4; i++) {
        int c = c0 + i;
        if (c < NCLASS) out[(size_t)row * NCLASS + c] = z[i] - lse;
    }
}

// -----------------------------------------------------------------------------
extern "C" void kernel_launch(void* const* d_in, const int* in_sizes, int n_in,
                              void* d_out, int out_size) {
    const float* x        = (const float*)d_in[0];
    const int*   adj_rows = (const int*)  d_in[1];
    const int*   adj_cols = (const int*)  d_in[2];
    const float* adj_vals = (const float*)d_in[3];
    const float* w1       = (const float*)d_in[4];
    const float* b1       = (const float*)d_in[5];
    const float* w2       = (const float*)d_in[6];
    const float* b2       = (const float*)d_in[7];
    float* out = (float*)d_out;
    const int nnz = in_sizes[1];

    void* buf1; cudaGetSymbolAddress(&buf1, g_buf1_v);
    void* buf2; cudaGetSymbolAddress(&buf2, g_buf2_v);
    uint32_t* w1p; cudaGetSymbolAddress((void**)&w1p, g_w1p);
    uint32_t* w2p; cudaGetSymbolAddress((void**)&w2p, g_w2p);

    cudaStream_t s2;
    cudaStreamCreateWithFlags(&s2, cudaStreamNonBlocking);
    cudaEvent_t ev1, ev2;
    cudaEventCreateWithFlags(&ev1, cudaEventDisableTiming);
    cudaEventCreateWithFlags(&ev2, cudaEventDisableTiming);

    // 1) CSR row pointers + packed weights (stream 0)
    build_rowptr<<<(NROWS + 1 + 255) / 256, 256>>>(adj_rows, nnz);
    prep_w<<<(W1PN_ELEMS + W2PN_ELEMS + 255) / 256, 256>>>(w1, w2);

    const int gemm_blocks = (NROWS + BM - 1) / BM;
    const int spmm_blocks = (NROWS + 7) / 8;

    // 2a) XW1 cols 0-127 (stream 0)
    sgemm_f16<<<gemm_blocks, 256>>>(x, w1p, (__half*)buf1, 0);
    cudaEventRecord(ev1, 0);

    // 3a) spmm1 chunk0 (stream s2) overlapped with 2b) XW1 cols 128-255 (stream 0)
    cudaStreamWaitEvent(s2, ev1, 0);
    spmm1_chunkh<<<spmm_blocks, 256, 0, s2>>>(adj_cols, adj_vals,
                                              (const uint2*)buf1, b1,
                                              (uint2*)buf2, 0);
    cudaEventRecord(ev2, s2);

    sgemm_f16<<<gemm_blocks, 256>>>(x, w1p, (__half*)buf1, 128);

    // 3b) spmm1 chunk1 (stream 0, after sgemm half1); join s2
    spmm1_chunkh<<<spmm_blocks, 256>>>(adj_cols, adj_vals,
                                       (const uint2*)buf1, b1,
                                       (uint2*)buf2, 1);
    cudaStreamWaitEvent(0, ev2, 0);

    // 4) t = h @ W2 -> buf1 (half, 48-pitch)
    gemm_t_h<<<(NROWS + TBM - 1) / TBM, 256>>>((const __half*)buf2, w2p,
                                               (__half*)buf1);

    // 5) out = log_softmax(A @ t + b2)
    spmm2_lsm<<<(NROWS + 15) / 16, 256>>>(adj_cols, adj_vals,
                                          (const uint2*)buf1, b2, out);

    cudaStreamDestroy(s2);   // deferred destruction; safe during capture lifetime
    cudaEventDestroy(ev1);
    cudaEventDestroy(ev2);
}

// round 14
// speedup vs baseline: 1.1276x; 1.1276x over previous
#include <cuda_runtime.h>
#include <cuda_fp16.h>
#include <cstdint>
#include <math.h>

#define NROWS   100000
#define NFEAT   512
#define NHID    256
#define NCLASS  41
#define TPH     48          // t row pitch in halves (41 used)
#define W2PN    64          // W2 padded cols

// ---------------- scratch (device globals) ----------------------------------
__device__ float4 g_buf1_v[(size_t)NROWS * NHID / 4];   // XW1 (half), then t (half)
__device__ float4 g_buf2_v[(size_t)NROWS * NHID / 4];   // h (half)
__device__ int    g_rowptr[NROWS + 1];
__device__ __align__(16) uint32_t g_w1p[(NFEAT / 2) * NHID];
__device__ __align__(16) uint32_t g_w2p[(NHID / 2) * W2PN];

// ---------------- row_ptr ----------------------------------------------------
__global__ void build_rowptr(const int* __restrict__ rows, int nnz) {
    int i = blockIdx.x * blockDim.x + threadIdx.x;
    if (i > NROWS) return;
    int lo = 0, hi = nnz;
    while (lo < hi) {
        int mid = (lo + hi) >> 1;
        if (rows[mid] < i) lo = mid + 1; else hi = mid;
    }
    g_rowptr[i] = lo;
}

// ---------------- mma helper ---------------------------------------------------
__device__ __forceinline__ void mma_f16(float* c, const uint32_t* a, const uint32_t* b) {
    asm volatile(
        "mma.sync.aligned.m16n8k16.row.col.f32.f16.f16.f32 "
        "{%0,%1,%2,%3}, {%4,%5,%6,%7}, {%8,%9}, {%0,%1,%2,%3};"
        : "+f"(c[0]), "+f"(c[1]), "+f"(c[2]), "+f"(c[3])
        : "r"(a[0]), "r"(a[1]), "r"(a[2]), "r"(a[3]),
          "r"(b[0]), "r"(b[1]));
}

// ---------------- prep: half2-packed W1 + W2 (merged) ------------------------
#define W1PN_ELEMS ((NFEAT / 2) * NHID)
#define W2PN_ELEMS ((NHID / 2) * W2PN)
__global__ void prep_w(const float* __restrict__ w1, const float* __restrict__ w2) {
    int i = blockIdx.x * blockDim.x + threadIdx.x;
    if (i < W1PN_ELEMS) {
        int k2 = i / NHID, n = i % NHID;
        __half2 u = __halves2half2(__float2half_rn(w1[(2 * k2) * NHID + n]),
                                   __float2half_rn(w1[(2 * k2 + 1) * NHID + n]));
        g_w1p[i] = *(uint32_t*)&u;
    } else if (i < W1PN_ELEMS + W2PN_ELEMS) {
        int j = i - W1PN_ELEMS;
        int k2 = j / W2PN, n = j % W2PN;
        __half2 u = (n < NCLASS)
            ? __halves2half2(__float2half_rn(w2[(2 * k2) * NCLASS + n]),
                             __float2half_rn(w2[(2 * k2 + 1) * NCLASS + n]))
            : __halves2half2(__float2half_rn(0.f), __float2half_rn(0.f));
        g_w2p[j] = *(uint32_t*)&u;
    }
}

// ---------------- SGEMM1: FP16 m16n8k16, double-buffered, half out -----------
#define BM 128
#define BN 128
#define FBK 32
#define SAP 20
#define SBP 136

__device__ __forceinline__ void f_ldgA(const float* A, int row0, int k0, int tid,
                                       float4 ra[4]) {
#pragma unroll
    for (int q = 0; q < 4; q++) {
        int idx = q * 256 + tid;
        int r = idx >> 3, c4 = (idx & 7) * 4;
        float4 v = {0.f, 0.f, 0.f, 0.f};
        if (row0 + r < NROWS)
            v = *(const float4*)(A + (size_t)(row0 + r) * NFEAT + k0 + c4);
        ra[q] = v;
    }
}
__device__ __forceinline__ void f_ldgB(const uint32_t* Bp, int col0, int k0, int tid,
                                       uint4 rb[2]) {
    int k20 = k0 / 2;
#pragma unroll
    for (int q = 0; q < 2; q++) {
        int idx = q * 256 + tid;
        int r = idx >> 5, c4 = (idx & 31) * 4;
        rb[q] = *(const uint4*)(Bp + (size_t)(k20 + r) * NHID + col0 + c4);
    }
}
__device__ __forceinline__ void f_sts(uint32_t (*sA)[SAP], uint32_t (*sB)[SBP],
                                      int tid, const float4 ra[4], const uint4 rb[2]) {
#pragma unroll
    for (int q = 0; q < 4; q++) {
        int idx = q * 256 + tid;
        int r = idx >> 3, c2 = (idx & 7) * 2;
        __half2 h0 = __floats2half2_rn(ra[q].x, ra[q].y);
        __half2 h1 = __floats2half2_rn(ra[q].z, ra[q].w);
        sA[r][c2]     = *(uint32_t*)&h0;
        sA[r][c2 + 1] = *(uint32_t*)&h1;
    }
#pragma unroll
    for (int q = 0; q < 2; q++) {
        int idx = q * 256 + tid;
        int r = idx >> 5, c4 = (idx & 31) * 4;
        *(uint4*)&sB[r][c4] = rb[q];
    }
}

__global__ __launch_bounds__(256) void sgemm_f16(const float* __restrict__ A,
                                                 const uint32_t* __restrict__ Bp,
                                                 __half* __restrict__ C) {
    __shared__ __align__(16) uint32_t sA[2][BM][SAP];
    __shared__ __align__(16) uint32_t sB[2][FBK / 2][SBP];

    const int tid  = threadIdx.x;
    const int lane = tid & 31;
    const int warp = tid >> 5;
    const int warp_m = warp & 1;
    const int warp_n = warp >> 1;
    const int row0 = blockIdx.y * BM;     // y=row, x=col: col tiles adjacent
    const int col0 = blockIdx.x * BN;
    const int tr = lane >> 2;
    const int tc = lane & 3;

    float acc[4][4][4];
#pragma unroll
    for (int i = 0; i < 4; i++)
#pragma unroll
        for (int j = 0; j < 4; j++)
#pragma unroll
            for (int q = 0; q < 4; q++) acc[i][j][q] = 0.f;

    float4 ra[4]; uint4 rb[2];
    f_ldgA(A, row0, 0, tid, ra);
    f_ldgB(Bp, col0, 0, tid, rb);
    f_sts(sA[0], sB[0], tid, ra, rb);
    __syncthreads();

    const int NT = NFEAT / FBK;
    for (int t = 0; t < NT; t++) {
        const int cur = t & 1;
        if (t + 1 < NT) {
            f_ldgA(A, row0, (t + 1) * FBK, tid, ra);
            f_ldgB(Bp, col0, (t + 1) * FBK, tid, rb);
        }
#pragma unroll
        for (int s = 0; s < 2; s++) {
            const int kb = s * 8;
            uint32_t bf[4][2];
#pragma unroll
            for (int wn = 0; wn < 4; wn++) {
                int n = warp_n * 32 + wn * 8 + tr;
                bf[wn][0] = sB[cur][kb + tc][n];
                bf[wn][1] = sB[cur][kb + tc + 4][n];
            }
#pragma unroll
            for (int wm = 0; wm < 4; wm++) {
                int m = warp_m * 64 + wm * 16 + tr;
                uint32_t af[4];
                af[0] = sA[cur][m][kb + tc];
                af[1] = sA[cur][m + 8][kb + tc];
                af[2] = sA[cur][m][kb + tc + 4];
                af[3] = sA[cur][m + 8][kb + tc + 4];
#pragma unroll
                for (int wn = 0; wn < 4; wn++)
                    mma_f16(acc[wm][wn], af, bf[wn]);
            }
        }
        if (t + 1 < NT)
            f_sts(sA[cur ^ 1], sB[cur ^ 1], tid, ra, rb);
        __syncthreads();
    }

#pragma unroll
    for (int wm = 0; wm < 4; wm++) {
        int r = row0 + warp_m * 64 + wm * 16 + tr;
#pragma unroll
        for (int wn = 0; wn < 4; wn++) {
            int c = col0 + warp_n * 32 + wn * 8 + tc * 2;
            if (r < NROWS) {
                __half2 hv = __floats2half2_rn(acc[wm][wn][0], acc[wm][wn][1]);
                *(uint32_t*)(C + (size_t)r * NHID + c) = *(uint32_t*)&hv;
            }
            if (r + 8 < NROWS) {
                __half2 hv = __floats2half2_rn(acc[wm][wn][2], acc[wm][wn][3]);
                *(uint32_t*)(C + (size_t)(r + 8) * NHID + c) = *(uint32_t*)&hv;
            }
        }
    }
}

// ---------------- SpMM layer 1: fp16 rows, single pass -----------------------
__global__ __launch_bounds__(256) void spmm1_h(const int* __restrict__ cols,
                                               const float* __restrict__ vals,
                                               const uint4* __restrict__ denseH,
                                               const float* __restrict__ bias,
                                               uint4* __restrict__ outH) {
    int row  = blockIdx.x * 8 + (threadIdx.x >> 5);
    if (row >= NROWS) return;
    int lane = threadIdx.x & 31;

    int s = g_rowptr[row];
    int e = g_rowptr[row + 1];

    float acc[8];
#pragma unroll
    for (int i = 0; i < 8; i++) acc[i] = 0.f;

    for (int j = s; j < e; j++) {
        int   c = __ldg(cols + j);
        float v = __ldg(vals + j);
        uint4 d = __ldg(denseH + (size_t)c * (NHID / 8) + lane);
        const uint32_t* dw = (const uint32_t*)&d;
#pragma unroll
        for (int i = 0; i < 4; i++) {
            float2 f = __half22float2(*(const __half2*)&dw[i]);
            acc[2 * i]     += v * f.x;
            acc[2 * i + 1] += v * f.y;
        }
    }

    const int c0 = lane * 8;
    float4 b0 = __ldg((const float4*)(bias + c0));
    float4 b1 = __ldg((const float4*)(bias + c0 + 4));
    acc[0] = fmaxf(acc[0] + b0.x, 0.f); acc[1] = fmaxf(acc[1] + b0.y, 0.f);
    acc[2] = fmaxf(acc[2] + b0.z, 0.f); acc[3] = fmaxf(acc[3] + b0.w, 0.f);
    acc[4] = fmaxf(acc[4] + b1.x, 0.f); acc[5] = fmaxf(acc[5] + b1.y, 0.f);
    acc[6] = fmaxf(acc[6] + b1.z, 0.f); acc[7] = fmaxf(acc[7] + b1.w, 0.f);

    uint4 o;
    uint32_t* ow = (uint32_t*)&o;
#pragma unroll
    for (int i = 0; i < 4; i++) {
        __half2 hv = __floats2half2_rn(acc[2 * i], acc[2 * i + 1]);
        ow[i] = *(uint32_t*)&hv;
    }
    outH[(size_t)row * (NHID / 8) + lane] = o;
}

// ---------------- t = h @ W2  fp16 m16n8k16 (128x64 tile) --------------------
#define TBM 128
#define TBK 64
#define TSAP 36
#define TSBP 72

__global__ __launch_bounds__(256) void gemm_t_h(const __half* __restrict__ H,
                                                const uint32_t* __restrict__ Bp,
                                                __half* __restrict__ T) {
    __shared__ __align__(16) uint32_t sA[TBM][TSAP];
    __shared__ __align__(16) uint32_t sB[TBK / 2][TSBP];

    const int tid  = threadIdx.x;
    const int lane = tid & 31;
    const int warp = tid >> 5;
    const int warp_m = warp & 1;
    const int warp_n = warp >> 1;
    const int row0 = blockIdx.x * TBM;
    const int tr = lane >> 2;
    const int tc = lane & 3;

    float acc[4][2][4];
#pragma unroll
    for (int i = 0; i < 4; i++)
#pragma unroll
        for (int j = 0; j < 2; j++)
#pragma unroll
            for (int q = 0; q < 4; q++) acc[i][j][q] = 0.f;

    for (int k0 = 0; k0 < NHID; k0 += TBK) {
#pragma unroll
        for (int q = 0; q < 4; q++) {
            int idx = q * 256 + tid;
            int r = idx >> 3, c8 = (idx & 7) * 8;
            uint4 v = {0u, 0u, 0u, 0u};
            if (row0 + r < NROWS)
                v = *(const uint4*)(H + (size_t)(row0 + r) * NHID + k0 + c8);
            *(uint4*)&sA[r][c8 / 2] = v;
        }
        {
            int k20 = k0 / 2;
#pragma unroll
            for (int q = 0; q < 2; q++) {
                int idx = q * 256 + tid;
                int r = idx >> 4, c4 = (idx & 15) * 4;
                *(uint4*)&sB[r][c4] = *(const uint4*)(Bp + (size_t)(k20 + r) * W2PN + c4);
            }
        }
        __syncthreads();

#pragma unroll
        for (int s = 0; s < 4; s++) {
            const int kb = s * 8;
            uint32_t bf[2][2];
#pragma unroll
            for (int wn = 0; wn < 2; wn++) {
                int n = warp_n * 16 + wn * 8 + tr;
                bf[wn][0] = sB[kb + tc][n];
                bf[wn][1] = sB[kb + tc + 4][n];
            }
#pragma unroll
            for (int wm = 0; wm < 4; wm++) {
                int m = warp_m * 64 + wm * 16 + tr;
                uint32_t af[4];
                af[0] = sA[m][kb + tc];
                af[1] = sA[m + 8][kb + tc];
                af[2] = sA[m][kb + tc + 4];
                af[3] = sA[m + 8][kb + tc + 4];
#pragma unroll
                for (int wn = 0; wn < 2; wn++)
                    mma_f16(acc[wm][wn], af, bf[wn]);
            }
        }
        __syncthreads();
    }

#pragma unroll
    for (int wm = 0; wm < 4; wm++) {
        int r = row0 + warp_m * 64 + wm * 16 + tr;
#pragma unroll
        for (int wn = 0; wn < 2; wn++) {
            int c = warp_n * 16 + wn * 8 + tc * 2;
            if (c < TPH) {
                if (r < NROWS) {
                    __half2 hv = __floats2half2_rn(acc[wm][wn][0], acc[wm][wn][1]);
                    *(uint32_t*)(T + (size_t)r * TPH + c) = *(uint32_t*)&hv;
                }
                if (r + 8 < NROWS) {
                    __half2 hv = __floats2half2_rn(acc[wm][wn][2], acc[wm][wn][3]);
                    *(uint32_t*)(T + (size_t)(r + 8) * TPH + c) = *(uint32_t*)&hv;
                }
            }
        }
    }
}

// ---------------- SpMM layer 2 + b2 + log_softmax (fp16 t, 2 rows/warp) ------
__global__ __launch_bounds__(256) void spmm2_lsm(const int* __restrict__ cols,
                                                 const float* __restrict__ vals,
                                                 const uint2* __restrict__ tH,
                                                 const float* __restrict__ b2,
                                                 float* __restrict__ out) {
    int lane   = threadIdx.x & 31;
    int lane16 = lane & 15;
    int row = blockIdx.x * 16 + (threadIdx.x >> 5) * 2 + (lane >> 4);
    if (row >= NROWS) return;
    const bool active = lane16 < (TPH / 4);    // 12 of 16 half-warp lanes

    int s = g_rowptr[row];
    int e = g_rowptr[row + 1];

    float acc[4] = {0.f, 0.f, 0.f, 0.f};
    for (int j = s; j < e; j++) {
        int   c = __ldg(cols + j);
        float v = __ldg(vals + j);
        if (active) {
            uint2 d = __ldg(tH + (size_t)c * (TPH / 4) + lane16);
            float2 f0 = __half22float2(*(const __half2*)&d.x);
            float2 f1 = __half22float2(*(const __half2*)&d.y);
            acc[0] += v * f0.x; acc[1] += v * f0.y;
            acc[2] += v * f1.x; acc[3] += v * f1.y;
        }
    }

    float z[4];
    const int c0 = lane16 * 4;
#pragma unroll
    for (int i = 0; i < 4; i++) {
        int c = c0 + i;
        z[i] = (active && c < NCLASS) ? (acc[i] + __ldg(b2 + c)) : -INFINITY;
    }
    float m = fmaxf(fmaxf(z[0], z[1]), fmaxf(z[2], z[3]));
#pragma unroll
    for (int off = 8; off; off >>= 1)
        m = fmaxf(m, __shfl_xor_sync(0xFFFFFFFFu, m, off));

    float ss = 0.f;
#pragma unroll
    for (int i = 0; i < 4; i++)
        if (c0 + i < NCLASS) ss += expf(z[i] - m);
#pragma unroll
    for (int off = 8; off; off >>= 1)
        ss += __shfl_xor_sync(0xFFFFFFFFu, ss, off);

    float lse = m + logf(ss);
#pragma unroll
    for (int i = 0; i < 4; i++) {
        int c = c0 + i;
        if (c < NCLASS) out[(size_t)row * NCLASS + c] = z[i] - lse;
    }
}

// -----------------------------------------------------------------------------
extern "C" void kernel_launch(void* const* d_in, const int* in_sizes, int n_in,
                              void* d_out, int out_size) {
    const float* x        = (const float*)d_in[0];
    const int*   adj_rows = (const int*)  d_in[1];
    const int*   adj_cols = (const int*)  d_in[2];
    const float* adj_vals = (const float*)d_in[3];
    const float* w1       = (const float*)d_in[4];
    const float* b1       = (const float*)d_in[5];
    const float* w2       = (const float*)d_in[6];
    const float* b2       = (const float*)d_in[7];
    float* out = (float*)d_out;
    const int nnz = in_sizes[1];

    void* buf1; cudaGetSymbolAddress(&buf1, g_buf1_v);
    void* buf2; cudaGetSymbolAddress(&buf2, g_buf2_v);
    uint32_t* w1p; cudaGetSymbolAddress((void**)&w1p, g_w1p);
    uint32_t* w2p; cudaGetSymbolAddress((void**)&w2p, g_w2p);

    // 1) CSR row pointers + packed weights
    build_rowptr<<<(NROWS + 1 + 255) / 256, 256>>>(adj_rows, nnz);
    prep_w<<<(W1PN_ELEMS + W2PN_ELEMS + 255) / 256, 256>>>(w1, w2);

    // 2) XW1 -> buf1 (half). grid: x=col tiles (2), y=row tiles -> A L2 reuse
    dim3 g1(NHID / BN, (NROWS + BM - 1) / BM);
    sgemm_f16<<<g1, 256>>>(x, w1p, (__half*)buf1);

    // 3) h = relu(A @ XW1 + b1) -> buf2 (half), single pass
    spmm1_h<<<(NROWS + 7) / 8, 256>>>(adj_cols, adj_vals, (const uint4*)buf1, b1,
                                      (uint4*)buf2);

    // 4) t = h @ W2 -> buf1 (half, 48-pitch)
    gemm_t_h<<<(NROWS + TBM - 1) / TBM, 256>>>((const __half*)buf2, w2p,
                                               (__half*)buf1);

    // 5) out = log_softmax(A @ t + b2)   (t: 9.6MB, L2-resident)
    spmm2_lsm<<<(NROWS + 15) / 16, 256>>>(adj_cols, adj_vals,
                                          (const uint2*)buf1, b2, out);
}

// round 15
// speedup vs baseline: 1.1282x; 1.0005x over previous
#include <cuda_runtime.h>
#include <cuda_fp16.h>
#include <cstdint>
#include <math.h>

#define NROWS   100000
#define NFEAT   512
#define NHID    256
#define NCLASS  41
#define TPH     48          // t row pitch in halves (41 used)
#define W2PN    64          // W2 padded cols
#define RHALF   50048       // row split point (mult of 128 and 8)

// ---------------- scratch (device globals) ----------------------------------
__device__ float4 g_buf1_v[(size_t)NROWS * NHID / 4];   // XW1 (half), then t (half)
__device__ float4 g_buf2_v[(size_t)NROWS * NHID / 4];   // h (half)
__device__ int    g_rowptr[NROWS + 1];
__device__ __align__(16) uint32_t g_w1p[(NFEAT / 2) * NHID];
__device__ __align__(16) uint32_t g_w2p[(NHID / 2) * W2PN];

// ---------------- mma helper ---------------------------------------------------
__device__ __forceinline__ void mma_f16(float* c, const uint32_t* a, const uint32_t* b) {
    asm volatile(
        "mma.sync.aligned.m16n8k16.row.col.f32.f16.f16.f32 "
        "{%0,%1,%2,%3}, {%4,%5,%6,%7}, {%8,%9}, {%0,%1,%2,%3};"
        : "+f"(c[0]), "+f"(c[1]), "+f"(c[2]), "+f"(c[3])
        : "r"(a[0]), "r"(a[1]), "r"(a[2]), "r"(a[3]),
          "r"(b[0]), "r"(b[1]));
}

// ---------------- prep: rowptr + packed W1 + W2 (single launch) --------------
#define W1PN_ELEMS ((NFEAT / 2) * NHID)
#define W2PN_ELEMS ((NHID / 2) * W2PN)
#define PREP_TOTAL (W1PN_ELEMS + W2PN_ELEMS + NROWS + 1)
__global__ void prep_all(const float* __restrict__ w1, const float* __restrict__ w2,
                         const int* __restrict__ rows, int nnz) {
    int i = blockIdx.x * blockDim.x + threadIdx.x;
    if (i < W1PN_ELEMS) {
        int k2 = i / NHID, n = i % NHID;
        __half2 u = __halves2half2(__float2half_rn(w1[(2 * k2) * NHID + n]),
                                   __float2half_rn(w1[(2 * k2 + 1) * NHID + n]));
        g_w1p[i] = *(uint32_t*)&u;
    } else if (i < W1PN_ELEMS + W2PN_ELEMS) {
        int j = i - W1PN_ELEMS;
        int k2 = j / W2PN, n = j % W2PN;
        __half2 u = (n < NCLASS)
            ? __halves2half2(__float2half_rn(w2[(2 * k2) * NCLASS + n]),
                             __float2half_rn(w2[(2 * k2 + 1) * NCLASS + n]))
            : __halves2half2(__float2half_rn(0.f), __float2half_rn(0.f));
        g_w2p[j] = *(uint32_t*)&u;
    } else if (i < PREP_TOTAL) {
        int r = i - W1PN_ELEMS - W2PN_ELEMS;       // 0..NROWS
        int lo = 0, hi = nnz;
        while (lo < hi) {
            int mid = (lo + hi) >> 1;
            if (rows[mid] < r) lo = mid + 1; else hi = mid;
        }
        g_rowptr[r] = lo;
    }
}

// ---------------- SGEMM1: FP16 m16n8k16, double-buffered, half out -----------
#define BM 128
#define BN 128
#define FBK 32
#define SAP 20
#define SBP 136

__device__ __forceinline__ void f_ldgA(const float* A, int row0, int k0, int tid,
                                       float4 ra[4]) {
#pragma unroll
    for (int q = 0; q < 4; q++) {
        int idx = q * 256 + tid;
        int r = idx >> 3, c4 = (idx & 7) * 4;
        float4 v = {0.f, 0.f, 0.f, 0.f};
        if (row0 + r < NROWS)
            v = *(const float4*)(A + (size_t)(row0 + r) * NFEAT + k0 + c4);
        ra[q] = v;
    }
}
__device__ __forceinline__ void f_ldgB(const uint32_t* Bp, int col0, int k0, int tid,
                                       uint4 rb[2]) {
    int k20 = k0 / 2;
#pragma unroll
    for (int q = 0; q < 2; q++) {
        int idx = q * 256 + tid;
        int r = idx >> 5, c4 = (idx & 31) * 4;
        rb[q] = *(const uint4*)(Bp + (size_t)(k20 + r) * NHID + col0 + c4);
    }
}
__device__ __forceinline__ void f_sts(uint32_t (*sA)[SAP], uint32_t (*sB)[SBP],
                                      int tid, const float4 ra[4], const uint4 rb[2]) {
#pragma unroll
    for (int q = 0; q < 4; q++) {
        int idx = q * 256 + tid;
        int r = idx >> 3, c2 = (idx & 7) * 2;
        __half2 h0 = __floats2half2_rn(ra[q].x, ra[q].y);
        __half2 h1 = __floats2half2_rn(ra[q].z, ra[q].w);
        sA[r][c2]     = *(uint32_t*)&h0;
        sA[r][c2 + 1] = *(uint32_t*)&h1;
    }
#pragma unroll
    for (int q = 0; q < 2; q++) {
        int idx = q * 256 + tid;
        int r = idx >> 5, c4 = (idx & 31) * 4;
        *(uint4*)&sB[r][c4] = rb[q];
    }
}

__global__ __launch_bounds__(256) void sgemm_f16(const float* __restrict__ A,
                                                 const uint32_t* __restrict__ Bp,
                                                 __half* __restrict__ C) {
    __shared__ __align__(16) uint32_t sA[2][BM][SAP];
    __shared__ __align__(16) uint32_t sB[2][FBK / 2][SBP];

    const int tid  = threadIdx.x;
    const int lane = tid & 31;
    const int warp = tid >> 5;
    const int warp_m = warp & 1;
    const int warp_n = warp >> 1;
    const int row0 = blockIdx.y * BM;     // y=row, x=col: col tiles adjacent
    const int col0 = blockIdx.x * BN;
    const int tr = lane >> 2;
    const int tc = lane & 3;

    float acc[4][4][4];
#pragma unroll
    for (int i = 0; i < 4; i++)
#pragma unroll
        for (int j = 0; j < 4; j++)
#pragma unroll
            for (int q = 0; q < 4; q++) acc[i][j][q] = 0.f;

    float4 ra[4]; uint4 rb[2];
    f_ldgA(A, row0, 0, tid, ra);
    f_ldgB(Bp, col0, 0, tid, rb);
    f_sts(sA[0], sB[0], tid, ra, rb);
    __syncthreads();

    const int NT = NFEAT / FBK;
    for (int t = 0; t < NT; t++) {
        const int cur = t & 1;
        if (t + 1 < NT) {
            f_ldgA(A, row0, (t + 1) * FBK, tid, ra);
            f_ldgB(Bp, col0, (t + 1) * FBK, tid, rb);
        }
#pragma unroll
        for (int s = 0; s < 2; s++) {
            const int kb = s * 8;
            uint32_t bf[4][2];
#pragma unroll
            for (int wn = 0; wn < 4; wn++) {
                int n = warp_n * 32 + wn * 8 + tr;
                bf[wn][0] = sB[cur][kb + tc][n];
                bf[wn][1] = sB[cur][kb + tc + 4][n];
            }
#pragma unroll
            for (int wm = 0; wm < 4; wm++) {
                int m = warp_m * 64 + wm * 16 + tr;
                uint32_t af[4];
                af[0] = sA[cur][m][kb + tc];
                af[1] = sA[cur][m + 8][kb + tc];
                af[2] = sA[cur][m][kb + tc + 4];
                af[3] = sA[cur][m + 8][kb + tc + 4];
#pragma unroll
                for (int wn = 0; wn < 4; wn++)
                    mma_f16(acc[wm][wn], af, bf[wn]);
            }
        }
        if (t + 1 < NT)
            f_sts(sA[cur ^ 1], sB[cur ^ 1], tid, ra, rb);
        __syncthreads();
    }

#pragma unroll
    for (int wm = 0; wm < 4; wm++) {
        int r = row0 + warp_m * 64 + wm * 16 + tr;
#pragma unroll
        for (int wn = 0; wn < 4; wn++) {
            int c = col0 + warp_n * 32 + wn * 8 + tc * 2;
            if (r < NROWS) {
                __half2 hv = __floats2half2_rn(acc[wm][wn][0], acc[wm][wn][1]);
                *(uint32_t*)(C + (size_t)r * NHID + c) = *(uint32_t*)&hv;
            }
            if (r + 8 < NROWS) {
                __half2 hv = __floats2half2_rn(acc[wm][wn][2], acc[wm][wn][3]);
                *(uint32_t*)(C + (size_t)(r + 8) * NHID + c) = *(uint32_t*)&hv;
            }
        }
    }
}

// ---------------- SpMM layer 1: fp16 rows, row-ranged -------------------------
__global__ __launch_bounds__(256) void spmm1_h(const int* __restrict__ cols,
                                               const float* __restrict__ vals,
                                               const uint4* __restrict__ denseH,
                                               const float* __restrict__ bias,
                                               uint4* __restrict__ outH,
                                               int rowbase, int rowend) {
    int row  = rowbase + blockIdx.x * 8 + (threadIdx.x >> 5);
    if (row >= rowend) return;
    int lane = threadIdx.x & 31;

    int s = g_rowptr[row];
    int e = g_rowptr[row + 1];

    float acc[8];
#pragma unroll
    for (int i = 0; i < 8; i++) acc[i] = 0.f;

    for (int j = s; j < e; j++) {
        int   c = __ldg(cols + j);
        float v = __ldg(vals + j);
        uint4 d = __ldg(denseH + (size_t)c * (NHID / 8) + lane);
        const uint32_t* dw = (const uint32_t*)&d;
#pragma unroll
        for (int i = 0; i < 4; i++) {
            float2 f = __half22float2(*(const __half2*)&dw[i]);
            acc[2 * i]     += v * f.x;
            acc[2 * i + 1] += v * f.y;
        }
    }

    const int c0 = lane * 8;
    float4 b0 = __ldg((const float4*)(bias + c0));
    float4 b1 = __ldg((const float4*)(bias + c0 + 4));
    acc[0] = fmaxf(acc[0] + b0.x, 0.f); acc[1] = fmaxf(acc[1] + b0.y, 0.f);
    acc[2] = fmaxf(acc[2] + b0.z, 0.f); acc[3] = fmaxf(acc[3] + b0.w, 0.f);
    acc[4] = fmaxf(acc[4] + b1.x, 0.f); acc[5] = fmaxf(acc[5] + b1.y, 0.f);
    acc[6] = fmaxf(acc[6] + b1.z, 0.f); acc[7] = fmaxf(acc[7] + b1.w, 0.f);

    uint4 o;
    uint32_t* ow = (uint32_t*)&o;
#pragma unroll
    for (int i = 0; i < 4; i++) {
        __half2 hv = __floats2half2_rn(acc[2 * i], acc[2 * i + 1]);
        ow[i] = *(uint32_t*)&hv;
    }
    outH[(size_t)row * (NHID / 8) + lane] = o;
}

// ---------------- t = h @ W2  fp16 m16n8k16 (128x64 tile), row-ranged ---------
#define TBM 128
#define TBK 64
#define TSAP 36
#define TSBP 72

__global__ __launch_bounds__(256) void gemm_t_h(const __half* __restrict__ H,
                                                const uint32_t* __restrict__ Bp,
                                                __half* __restrict__ T,
                                                int rowbase) {
    __shared__ __align__(16) uint32_t sA[TBM][TSAP];
    __shared__ __align__(16) uint32_t sB[TBK / 2][TSBP];

    const int tid  = threadIdx.x;
    const int lane = tid & 31;
    const int warp = tid >> 5;
    const int warp_m = warp & 1;
    const int warp_n = warp >> 1;
    const int row0 = rowbase + blockIdx.x * TBM;
    const int tr = lane >> 2;
    const int tc = lane & 3;

    float acc[4][2][4];
#pragma unroll
    for (int i = 0; i < 4; i++)
#pragma unroll
        for (int j = 0; j < 2; j++)
#pragma unroll
            for (int q = 0; q < 4; q++) acc[i][j][q] = 0.f;

    for (int k0 = 0; k0 < NHID; k0 += TBK) {
#pragma unroll
        for (int q = 0; q < 4; q++) {
            int idx = q * 256 + tid;
            int r = idx >> 3, c8 = (idx & 7) * 8;
            uint4 v = {0u, 0u, 0u, 0u};
            if (row0 + r < NROWS)
                v = *(const uint4*)(H + (size_t)(row0 + r) * NHID + k0 + c8);
            *(uint4*)&sA[r][c8 / 2] = v;
        }
        {
            int k20 = k0 / 2;
#pragma unroll
            for (int q = 0; q < 2; q++) {
                int idx = q * 256 + tid;
                int r = idx >> 4, c4 = (idx & 15) * 4;
                *(uint4*)&sB[r][c4] = *(const uint4*)(Bp + (size_t)(k20 + r) * W2PN + c4);
            }
        }
        __syncthreads();

#pragma unroll
        for (int s = 0; s < 4; s++) {
            const int kb = s * 8;
            uint32_t bf[2][2];
#pragma unroll
            for (int wn = 0; wn < 2; wn++) {
                int n = warp_n * 16 + wn * 8 + tr;
                bf[wn][0] = sB[kb + tc][n];
                bf[wn][1] = sB[kb + tc + 4][n];
            }
#pragma unroll
            for (int wm = 0; wm < 4; wm++) {
                int m = warp_m * 64 + wm * 16 + tr;
                uint32_t af[4];
                af[0] = sA[m][kb + tc];
                af[1] = sA[m + 8][kb + tc];
                af[2] = sA[m][kb + tc + 4];
                af[3] = sA[m + 8][kb + tc + 4];
#pragma unroll
                for (int wn = 0; wn < 2; wn++)
                    mma_f16(acc[wm][wn], af, bf[wn]);
            }
        }
        __syncthreads();
    }

#pragma unroll
    for (int wm = 0; wm < 4; wm++) {
        int r = row0 + warp_m * 64 + wm * 16 + tr;
#pragma unroll
        for (int wn = 0; wn < 2; wn++) {
            int c = warp_n * 16 + wn * 8 + tc * 2;
            if (c < TPH) {
                if (r < NROWS) {
                    __half2 hv = __floats2half2_rn(acc[wm][wn][0], acc[wm][wn][1]);
                    *(uint32_t*)(T + (size_t)r * TPH + c) = *(uint32_t*)&hv;
                }
                if (r + 8 < NROWS) {
                    __half2 hv = __floats2half2_rn(acc[wm][wn][2], acc[wm][wn][3]);
                    *(uint32_t*)(T + (size_t)(r + 8) * TPH + c) = *(uint32_t*)&hv;
                }
            }
        }
    }
}

// ---------------- SpMM layer 2 + b2 + log_softmax (fp16 t, 2 rows/warp) ------
__global__ __launch_bounds__(256) void spmm2_lsm(const int* __restrict__ cols,
                                                 const float* __restrict__ vals,
                                                 const uint2* __restrict__ tH,
                                                 const float* __restrict__ b2,
                                                 float* __restrict__ out) {
    int lane   = threadIdx.x & 31;
    int lane16 = lane & 15;
    int row = blockIdx.x * 16 + (threadIdx.x >> 5) * 2 + (lane >> 4);
    if (row >= NROWS) return;
    const bool active = lane16 < (TPH / 4);    // 12 of 16 half-warp lanes

    int s = g_rowptr[row];
    int e = g_rowptr[row + 1];

    float acc[4] = {0.f, 0.f, 0.f, 0.f};
    for (int j = s; j < e; j++) {
        int   c = __ldg(cols + j);
        float v = __ldg(vals + j);
        if (active) {
            uint2 d = __ldg(tH + (size_t)c * (TPH / 4) + lane16);
            float2 f0 = __half22float2(*(const __half2*)&d.x);
            float2 f1 = __half22float2(*(const __half2*)&d.y);
            acc[0] += v * f0.x; acc[1] += v * f0.y;
            acc[2] += v * f1.x; acc[3] += v * f1.y;
        }
    }

    float z[4];
    const int c0 = lane16 * 4;
#pragma unroll
    for (int i = 0; i < 4; i++) {
        int c = c0 + i;
        z[i] = (active && c < NCLASS) ? (acc[i] + __ldg(b2 + c)) : -INFINITY;
    }
    float m = fmaxf(fmaxf(z[0], z[1]), fmaxf(z[2], z[3]));
#pragma unroll
    for (int off = 8; off; off >>= 1)
        m = fmaxf(m, __shfl_xor_sync(0xFFFFFFFFu, m, off));

    float ss = 0.f;
#pragma unroll
    for (int i = 0; i < 4; i++)
        if (c0 + i < NCLASS) ss += expf(z[i] - m);
#pragma unroll
    for (int off = 8; off; off >>= 1)
        ss += __shfl_xor_sync(0xFFFFFFFFu, ss, off);

    float lse = m + logf(ss);
#pragma unroll
    for (int i = 0; i < 4; i++) {
        int c = c0 + i;
        if (c < NCLASS) out[(size_t)row * NCLASS + c] = z[i] - lse;
    }
}

// -----------------------------------------------------------------------------
extern "C" void kernel_launch(void* const* d_in, const int* in_sizes, int n_in,
                              void* d_out, int out_size) {
    const float* x        = (const float*)d_in[0];
    const int*   adj_rows = (const int*)  d_in[1];
    const int*   adj_cols = (const int*)  d_in[2];
    const float* adj_vals = (const float*)d_in[3];
    const float* w1       = (const float*)d_in[4];
    const float* b1       = (const float*)d_in[5];
    const float* w2       = (const float*)d_in[6];
    const float* b2       = (const float*)d_in[7];
    float* out = (float*)d_out;
    const int nnz = in_sizes[1];

    void* buf1; cudaGetSymbolAddress(&buf1, g_buf1_v);
    void* buf2; cudaGetSymbolAddress(&buf2, g_buf2_v);
    uint32_t* w1p; cudaGetSymbolAddress((void**)&w1p, g_w1p);
    uint32_t* w2p; cudaGetSymbolAddress((void**)&w2p, g_w2p);

    cudaStream_t s2;
    cudaStreamCreateWithFlags(&s2, cudaStreamNonBlocking);
    cudaEvent_t ev1, ev2;
    cudaEventCreateWithFlags(&ev1, cudaEventDisableTiming);
    cudaEventCreateWithFlags(&ev2, cudaEventDisableTiming);

    // 1) rowptr + packed weights (single launch)
    prep_all<<<(PREP_TOTAL + 255) / 256, 256>>>(w1, w2, adj_rows, nnz);

    // 2) XW1 -> buf1 (half); col tiles adjacent -> A read once
    dim3 g1(NHID / BN, (NROWS + BM - 1) / BM);
    sgemm_f16<<<g1, 256>>>(x, w1p, (__half*)buf1);

    // 3) spmm1 first half rows, then fork:
    spmm1_h<<<RHALF / 8, 256>>>(adj_cols, adj_vals, (const uint4*)buf1, b1,
                                (uint4*)buf2, 0, RHALF);
    cudaEventRecord(ev1, 0);

    //    gemm_t on first-half rows (s2) overlaps spmm1 second half (stream 0)
    cudaStreamWaitEvent(s2, ev1, 0);
    gemm_t_h<<<RHALF / TBM, 256, 0, s2>>>((const __half*)buf2, w2p,
                                          (__half*)buf1, 0);
    cudaEventRecord(ev2, s2);

    spmm1_h<<<(NROWS - RHALF + 7) / 8, 256>>>(adj_cols, adj_vals,
                                              (const uint4*)buf1, b1,
                                              (uint4*)buf2, RHALF, NROWS);

    // 4) gemm_t second half (stream 0), join s2
    gemm_t_h<<<(NROWS - RHALF + TBM - 1) / TBM, 256>>>((const __half*)buf2, w2p,
                                                       (__half*)buf1, RHALF);
    cudaStreamWaitEvent(0, ev2, 0);

    // 5) out = log_softmax(A @ t + b2)
    spmm2_lsm<<<(NROWS + 15) / 16, 256>>>(adj_cols, adj_vals,
                                          (const uint2*)buf1, b2, out);

    cudaStreamDestroy(s2);
    cudaEventDestroy(ev1);
    cudaEventDestroy(ev2);
}